// round 17
// baseline (speedup 1.0000x reference)
#include <cuda_runtime.h>
#include <cuda_fp16.h>
#include <cstdint>

// YOLO decode layer: B=16, A=3, C=80, H=W=76.
// in  : (B, A*(C+5), H, W) fp32 = (16, 255, 76, 76)   ~94.3 MB
// out : (B, A, H, W, 7)    fp32                        ~7.8 MB
//
// R17: R16 compute (float2 = 2 positions/thread; ex2.approx.f16x2 softmax
// sum with fp32 log2e scaling; exact fp32 even/odd argmax chains with
// first-occurrence tie semantics; evict_last policy loads) + coalesced
// store staging: R16's stores scattered 8B writes at 56B thread stride
// (~4x sector amplification, ~31MB of store traffic). Now each block
// stages its 7168B output tile in smem and writes it back as 448
// consecutive float4 -> full-sector coalesced STG.128, 7.8MB true traffic.
// NPAIRS = 1083*128 exactly: all blocks full, __syncthreads is uniform.

constexpr int A_  = 3;
constexpr int C_  = 80;
constexpr int H_  = 76;
constexpr int W_  = 76;
constexpr int HW_ = H_ * W_;            // 5776
constexpr int NCH_ = C_ + 5;            // 85
constexpr int B_  = 16;
constexpr int PAIRS_PER_N = HW_ / 2;    // 2888
constexpr int NPAIRS = B_ * A_ * PAIRS_PER_N;  // 138624 = 1083 * 128
constexpr int BLOCK = 128;
constexpr int FLOATS_PER_BLOCK = BLOCK * 14;   // 1792 floats = 7168 B

__device__ __forceinline__ float fsig(float x) {
    return __fdividef(1.0f, 1.0f + __expf(-x));
}

__device__ __forceinline__ float2 ld_el(const float2* p, uint64_t pol) {
    float2 v;
    asm("ld.global.nc.L2::cache_hint.v2.f32 {%0,%1}, [%2], %3;"
        : "=f"(v.x), "=f"(v.y) : "l"(p), "l"(pol));
    return v;
}

__device__ __forceinline__ void st_cs4(float4* p, float4 v) {
    asm volatile("st.global.cs.v4.f32 [%0], {%1,%2,%3,%4};"
                 :: "l"(p), "f"(v.x), "f"(v.y), "f"(v.z), "f"(v.w));
}

__device__ __forceinline__ uint32_t pack_h2(float x, float y) {
    uint32_t d;
    asm("cvt.rn.f16x2.f32 %0, %1, %2;" : "=r"(d) : "f"(y), "f"(x));
    return d;
}
__device__ __forceinline__ uint32_t ex2_h2(uint32_t x) {
    uint32_t d;
    asm("ex2.approx.f16x2 %0, %1;" : "=r"(d) : "r"(x));
    return d;
}
__device__ __forceinline__ uint32_t hadd2(uint32_t a, uint32_t b) {
    uint32_t d;
    asm("add.rn.f16x2 %0, %1, %2;" : "=r"(d) : "r"(a), "r"(b));
    return d;
}

__global__ void __launch_bounds__(BLOCK) yolo_kernel(
    const float* __restrict__ in,
    const float* __restrict__ anchors,
    float* __restrict__ out)
{
    __shared__ float obuf[FLOATS_PER_BLOCK];

    int tid = threadIdx.x;
    int g = blockIdx.x * BLOCK + tid;   // grid exact (1083*128), no guard

    uint64_t pol;
    asm("createpolicy.fractional.L2::evict_last.b64 %0, 1.0;" : "=l"(pol));

    int n  = g / PAIRS_PER_N;           // flattened (b, a) index, 0..47
    int pr = g - n * PAIRS_PER_N;
    int hw = pr * 2;
    int a  = n % A_;

    float aw = anchors[2 * a + 0];
    float ah = anchors[2 * a + 1];

    int gy = hw / W_;                   // W even -> both positions same row
    int gx = hw - gy * W_;

    const float2* b2 = reinterpret_cast<const float2*>(in)
                     + (size_t)n * (NCH_ * PAIRS_PER_N) + pr;
    const float2* cb = b2 + 5 * PAIRS_PER_N;

    const float K = 1.4426950408889634f;   // log2(e)
    float m0 = -1e30f, m1 = -1e30f;
    int  id0 = 0, id1 = 0;
    uint32_t accA = 0u, accB = 0u;

    // box channels 0..4
    float2 bx[5];
    #pragma unroll
    for (int c = 0; c < 5; ++c)
        bx[c] = ld_el(b2 + (size_t)c * PAIRS_PER_N, pol);

    // class channels, two batched phases of 40
    float2 cl[40];
    #pragma unroll
    for (int i = 0; i < 40; ++i)
        cl[i] = ld_el(cb + (size_t)i * PAIRS_PER_N, pol);

    #pragma unroll
    for (int i = 0; i < 40; i += 2) {
        float2 ca = cl[i];
        float2 cc = cl[i + 1];
        if (ca.x > m0) { m0 = ca.x; id0 = i; }
        if (cc.x > m0) { m0 = cc.x; id0 = i + 1; }
        if (ca.y > m1) { m1 = ca.y; id1 = i; }
        if (cc.y > m1) { m1 = cc.y; id1 = i + 1; }
        accA = hadd2(accA, ex2_h2(pack_h2(ca.x * K, ca.y * K)));
        accB = hadd2(accB, ex2_h2(pack_h2(cc.x * K, cc.y * K)));
    }

    #pragma unroll
    for (int i = 0; i < 40; ++i)
        cl[i] = ld_el(cb + (size_t)(40 + i) * PAIRS_PER_N, pol);

    #pragma unroll
    for (int i = 0; i < 40; i += 2) {
        float2 ca = cl[i];
        float2 cc = cl[i + 1];
        int ch = 40 + i;
        if (ca.x > m0) { m0 = ca.x; id0 = ch; }
        if (cc.x > m0) { m0 = cc.x; id0 = ch + 1; }
        if (ca.y > m1) { m1 = ca.y; id1 = ch; }
        if (cc.y > m1) { m1 = cc.y; id1 = ch + 1; }
        accA = hadd2(accA, ex2_h2(pack_h2(ca.x * K, ca.y * K)));
        accB = hadd2(accB, ex2_h2(pack_h2(cc.x * K, cc.y * K)));
    }

    uint32_t acc = hadd2(accA, accB);
    __half2 hs = *reinterpret_cast<__half2*>(&acc);
    float s0 = __low2float(hs);
    float s1 = __high2float(hs);

    const float invW = 1.0f / (float)W_;
    const float invH = 1.0f / (float)H_;

    float xv[2]  = {bx[0].x, bx[0].y};
    float yv[2]  = {bx[1].x, bx[1].y};
    float wv[2]  = {bx[2].x, bx[2].y};
    float hv[2]  = {bx[3].x, bx[3].y};
    float cv4[2] = {bx[4].x, bx[4].y};
    float mm[2]  = {m0, m1};
    float ss[2]  = {s0, s1};
    int   idv[2] = {id0, id1};

    // stage 14 floats into smem (2-way bank conflicts worst case)
    float2* s2 = reinterpret_cast<float2*>(obuf) + tid * 7;
    #pragma unroll
    for (int j = 0; j < 2; ++j) {
        float o0 = (fsig(xv[j]) + (float)(gx + j)) * invW;
        float o1 = (fsig(yv[j]) + (float)gy) * invH;
        float o2 = __expf(wv[j]) * aw * invW;
        float o3 = __expf(hv[j]) * ah * invH;
        float o4 = fsig(cv4[j]);
        float o5 = __fdividef(__expf(mm[j]), ss[j]);
        float o6 = (float)idv[j];
        if (j == 0) {
            s2[0] = make_float2(o0, o1);
            s2[1] = make_float2(o2, o3);
            s2[2] = make_float2(o4, o5);
            s2[3] = make_float2(o6, 0.f);   // .y overwritten below
        } else {
            // pair layout: floats [7..13] of this thread's 14
            obuf[tid * 14 + 7]  = o0;
            obuf[tid * 14 + 8]  = o1;
            obuf[tid * 14 + 9]  = o2;
            obuf[tid * 14 + 10] = o3;
            obuf[tid * 14 + 11] = o4;
            obuf[tid * 14 + 12] = o5;
            obuf[tid * 14 + 13] = o6;
        }
    }
    __syncthreads();

    // coalesced block copy: 448 float4 = 7168 B contiguous
    const float4* s4 = reinterpret_cast<const float4*>(obuf);
    float4* g4 = reinterpret_cast<float4*>(out)
               + (size_t)blockIdx.x * (FLOATS_PER_BLOCK / 4);
    #pragma unroll
    for (int i = tid; i < FLOATS_PER_BLOCK / 4; i += BLOCK)
        st_cs4(g4 + i, s4[i]);
}

extern "C" void kernel_launch(void* const* d_in, const int* in_sizes, int n_in,
                              void* d_out, int out_size) {
    const float* in      = (const float*)d_in[0];
    const float* anchors = (const float*)d_in[1];
    float* out           = (float*)d_out;
    (void)in_sizes; (void)n_in; (void)out_size;

    yolo_kernel<<<NPAIRS / BLOCK, BLOCK>>>(in, anchors, out);
}